// round 2
// baseline (speedup 1.0000x reference)
#include <cuda_runtime.h>
#include <math.h>

#define BB 4
#define SS 512
#define JJ 24
#define HH 128
#define NN 8
#define DD 16
#define FDIM 256

constexpr long long E   = (long long)BB * SS * JJ * HH;   // 6291456 elements per (B,S,J,H) tensor
constexpr long long WSZ = (long long)JJ * HH * HH;        // 393216 per packed per-joint weight
constexpr long long WJS = (long long)HH * HH;             // per-joint stride inside a packed weight

// scratch layout inside one big device buffer
constexpr long long OFF_QT   = 0 * E;   // [b][j][s][c] temporal Q
constexpr long long OFF_KT   = 1 * E;
constexpr long long OFF_VT   = 2 * E;
constexpr long long OFF_OT   = 3 * E;   // [b][s][j][c] temporal attn out
constexpr long long OFF_TMP  = 4 * E;   // pre-LN staging
constexpr long long OFF_TOUT = 5 * E;
constexpr long long OFF_QS   = 6 * E;   // [b][s][j][c]
constexpr long long OFF_KS   = 7 * E;
constexpr long long OFF_VS   = 8 * E;
constexpr long long OFF_OS   = 9 * E;
constexpr long long OFF_SOUT = 10 * E;
constexpr long long OFF_A    = 11 * E;
constexpr long long OFF_FFB  = 12 * E;  // [49152][256] = 2*E
constexpr long long OFF_WQT  = 14 * E;
constexpr long long OFF_WKT  = OFF_WQT + 1 * WSZ;
constexpr long long OFF_WVT  = OFF_WQT + 2 * WSZ;
constexpr long long OFF_WQS  = OFF_WQT + 3 * WSZ;
constexpr long long OFF_WKS  = OFF_WQT + 4 * WSZ;
constexpr long long OFF_WVS  = OFF_WKS + (long long)HH * HH;
constexpr long long TOTAL    = OFF_WVS + (long long)HH * HH;

__device__ float g_scratch[TOTAL];

// ---------------------------------------------------------------------------
// Pack per-head weights (N,J,H,HS)->[j][h][c=n*16+d], (N,H,HS)->[h][c]
// ---------------------------------------------------------------------------
__global__ void pack_weights(const float* __restrict__ qt, const float* __restrict__ kt,
                             const float* __restrict__ vt, const float* __restrict__ qs,
                             const float* __restrict__ ks, const float* __restrict__ vs,
                             float* __restrict__ g) {
    int idx = blockIdx.x * blockDim.x + threadIdx.x;
    if (idx < (int)WSZ) {
        int j = idx / (HH * HH);
        int h = (idx / HH) % HH;
        int c = idx % HH;
        int n = c / DD, d = c % DD;
        long long src = (((long long)n * JJ + j) * HH + h) * DD + d;
        g[OFF_WQT + idx] = qt[src];
        g[OFF_WKT + idx] = kt[src];
        g[OFF_WVT + idx] = vt[src];
        g[OFF_WQS + idx] = qs[src];
    }
    if (idx < HH * HH) {
        int h = idx / HH, c = idx % HH;
        int n = c / DD, d = c % DD;
        long long src = ((long long)n * HH + h) * DD + d;
        g[OFF_WKS + idx] = ks[src];
        g[OFF_WVS + idx] = vs[src];
    }
}

// ---------------------------------------------------------------------------
// Generic tiled GEMM: C[row][col] = sum_k A[row][k] * W[k][col]  (+bias)(+relu)
// BM=128 BN=128 BK=16, 256 threads, 8x8 per thread.
// Row r of A at A0 + j*aJ + r*lda.
// Row r of C at C0 + j*cJ + (r/rdiv)*cHi + (r%rdiv)*cLo, col offset zt*128.
// W tile at W0 + j*wJ + zt*128, row stride ldw.
// ---------------------------------------------------------------------------
__launch_bounds__(256, 2)
__global__ void gemm128(const float* __restrict__ A0, long long aJ, int lda,
                        const float* __restrict__ W0, long long wJ, int ldw,
                        float* __restrict__ C0, long long cJ,
                        int K, int rdiv, long long cHi, long long cLo,
                        const float* __restrict__ bias, int doRelu) {
    __shared__ float As[16][132];   // [k][r], padded
    __shared__ float Ws[16][128];   // [k][c]

    int j  = blockIdx.y;
    int zt = blockIdx.z;
    const float* A = A0 + (long long)j * aJ;
    const float* W = W0 + (long long)j * wJ + zt * 128;
    int row0 = blockIdx.x * 128;
    int tid  = threadIdx.x;
    int tx = tid & 15;        // col group: cols tx*8 .. tx*8+7
    int ty = tid >> 4;        // row group: rows ty*8 .. ty*8+7

    int la_r = tid >> 2;           // 0..63 (+64 second pass)
    int la_k = (tid & 3) * 4;
    int lw_k = tid >> 5;           // 0..7 (+8 second pass)
    int lw_c = (tid & 31) * 4;

    float acc[8][8];
#pragma unroll
    for (int i = 0; i < 8; i++)
#pragma unroll
        for (int c = 0; c < 8; c++) acc[i][c] = 0.f;

    for (int k0 = 0; k0 < K; k0 += 16) {
#pragma unroll
        for (int p = 0; p < 2; p++) {
            int r = la_r + p * 64;
            float4 v = *(const float4*)(A + (long long)(row0 + r) * lda + k0 + la_k);
            As[la_k + 0][r] = v.x;
            As[la_k + 1][r] = v.y;
            As[la_k + 2][r] = v.z;
            As[la_k + 3][r] = v.w;
        }
#pragma unroll
        for (int p = 0; p < 2; p++) {
            int kk = lw_k + p * 8;
            float4 v = *(const float4*)(W + (long long)(k0 + kk) * ldw + lw_c);
            *(float4*)&Ws[kk][lw_c] = v;
        }
        __syncthreads();
#pragma unroll
        for (int kk = 0; kk < 16; kk++) {
            float af[8], wf[8];
            *(float4*)&af[0] = *(const float4*)&As[kk][ty * 8];
            *(float4*)&af[4] = *(const float4*)&As[kk][ty * 8 + 4];
            *(float4*)&wf[0] = *(const float4*)&Ws[kk][tx * 8];
            *(float4*)&wf[4] = *(const float4*)&Ws[kk][tx * 8 + 4];
#pragma unroll
            for (int i = 0; i < 8; i++)
#pragma unroll
                for (int c = 0; c < 8; c++) acc[i][c] += af[i] * wf[c];
        }
        __syncthreads();
    }

    int cc = tx * 8;
#pragma unroll
    for (int i = 0; i < 8; i++) {
        int r = row0 + ty * 8 + i;
        float* Cr = C0 + (long long)j * cJ + (long long)(r / rdiv) * cHi +
                    (long long)(r % rdiv) * cLo + (long long)zt * 128;
        float v[8];
#pragma unroll
        for (int c = 0; c < 8; c++) {
            float t = acc[i][c];
            if (bias) t += bias[zt * 128 + cc + c];
            if (doRelu) t = fmaxf(t, 0.f);
            v[c] = t;
        }
        *(float4*)&Cr[cc]     = make_float4(v[0], v[1], v[2], v[3]);
        *(float4*)&Cr[cc + 4] = make_float4(v[4], v[5], v[6], v[7]);
    }
}

// ---------------------------------------------------------------------------
// Temporal causal attention: one block per (b,j,n), 256 threads, 2 rows/thread.
// Q/K/V layout [b][j][s][c], c = n*16+d. Output O[b][s][j][c].
// ---------------------------------------------------------------------------
__global__ void temporal_attn(const float* __restrict__ Q, const float* __restrict__ Kt,
                              const float* __restrict__ V, float* __restrict__ O) {
    extern __shared__ float sm[];
    float* Ksm = sm;               // 512*16
    float* Vsm = sm + SS * DD;

    int n  = blockIdx.y;
    int bj = blockIdx.z;
    int b = bj / JJ, j = bj % JJ;
    long long base = (long long)bj * SS * HH;
    int tid = threadIdx.x;
    int co = n * 16;

    for (int i = tid; i < SS * DD / 4; i += 256) {
        int t = i >> 2, dq = i & 3;
        *(float4*)&Ksm[t * 16 + dq * 4] = *(const float4*)&Kt[base + (long long)t * HH + co + dq * 4];
        *(float4*)&Vsm[t * 16 + dq * 4] = *(const float4*)&V[base + (long long)t * HH + co + dq * 4];
    }
    __syncthreads();

    int s0 = tid, s1 = tid + 256;
    float q0[16], q1[16];
#pragma unroll
    for (int dq = 0; dq < 4; dq++) {
        *(float4*)&q0[dq * 4] = *(const float4*)&Q[base + (long long)s0 * HH + co + dq * 4];
        *(float4*)&q1[dq * 4] = *(const float4*)&Q[base + (long long)s1 * HH + co + dq * 4];
    }
    float o0[16], o1[16];
#pragma unroll
    for (int d = 0; d < 16; d++) { o0[d] = 0.f; o1[d] = 0.f; }
    float m0 = -1e30f, m1 = -1e30f, l0 = 0.f, l1 = 0.f;

    for (int t = 0; t <= s1; t++) {
        float kf[16], vf[16];
#pragma unroll
        for (int dq = 0; dq < 4; dq++) {
            *(float4*)&kf[dq * 4] = *(const float4*)&Ksm[t * 16 + dq * 4];
            *(float4*)&vf[dq * 4] = *(const float4*)&Vsm[t * 16 + dq * 4];
        }
        // row1
        {
            float a0 = 0, a1 = 0, a2 = 0, a3 = 0;
#pragma unroll
            for (int d = 0; d < 16; d += 4) {
                a0 += q1[d] * kf[d];
                a1 += q1[d + 1] * kf[d + 1];
                a2 += q1[d + 2] * kf[d + 2];
                a3 += q1[d + 3] * kf[d + 3];
            }
            float sc = ((a0 + a1) + (a2 + a3)) * 0.25f;
            if (sc > m1) {
                float corr = __expf(m1 - sc);
                l1 = l1 * corr + 1.f;
#pragma unroll
                for (int d = 0; d < 16; d++) o1[d] = o1[d] * corr + vf[d];
                m1 = sc;
            } else {
                float p = __expf(sc - m1);
                l1 += p;
#pragma unroll
                for (int d = 0; d < 16; d++) o1[d] += p * vf[d];
            }
        }
        // row0 (causal)
        if (t <= s0) {
            float a0 = 0, a1 = 0, a2 = 0, a3 = 0;
#pragma unroll
            for (int d = 0; d < 16; d += 4) {
                a0 += q0[d] * kf[d];
                a1 += q0[d + 1] * kf[d + 1];
                a2 += q0[d + 2] * kf[d + 2];
                a3 += q0[d + 3] * kf[d + 3];
            }
            float sc = ((a0 + a1) + (a2 + a3)) * 0.25f;
            if (sc > m0) {
                float corr = __expf(m0 - sc);
                l0 = l0 * corr + 1.f;
#pragma unroll
                for (int d = 0; d < 16; d++) o0[d] = o0[d] * corr + vf[d];
                m0 = sc;
            } else {
                float p = __expf(sc - m0);
                l0 += p;
#pragma unroll
                for (int d = 0; d < 16; d++) o0[d] += p * vf[d];
            }
        }
    }
    float i0 = 1.f / l0, i1 = 1.f / l1;
    long long ob0 = ((long long)(b * SS + s0) * JJ + j) * HH + co;
    long long ob1 = ((long long)(b * SS + s1) * JJ + j) * HH + co;
#pragma unroll
    for (int dq = 0; dq < 4; dq++) {
        *(float4*)&O[ob0 + dq * 4] = make_float4(o0[dq * 4] * i0, o0[dq * 4 + 1] * i0,
                                                 o0[dq * 4 + 2] * i0, o0[dq * 4 + 3] * i0);
        *(float4*)&O[ob1 + dq * 4] = make_float4(o1[dq * 4] * i1, o1[dq * 4 + 1] * i1,
                                                 o1[dq * 4 + 2] * i1, o1[dq * 4 + 3] * i1);
    }
}

// ---------------------------------------------------------------------------
// Spatial attention: one block per (b,s). 192 active threads = (n, jq).
// Q/K/V layout [b][s][j][c]. Output same layout.
// ---------------------------------------------------------------------------
__global__ void spatial_attn(const float* __restrict__ Q, const float* __restrict__ K,
                             const float* __restrict__ V, float* __restrict__ O) {
    __shared__ float Qs[JJ * HH], Ks[JJ * HH], Vs[JJ * HH];
    long long base = (long long)blockIdx.x * JJ * HH;
    int tid = threadIdx.x;
    for (int i = tid; i < JJ * HH / 4; i += 256) {
        ((float4*)Qs)[i] = ((const float4*)(Q + base))[i];
        ((float4*)Ks)[i] = ((const float4*)(K + base))[i];
        ((float4*)Vs)[i] = ((const float4*)(V + base))[i];
    }
    __syncthreads();
    if (tid < NN * JJ) {
        int n = tid / JJ, jq = tid % JJ;
        int co = n * 16;
        float q[16];
#pragma unroll
        for (int d = 0; d < 16; d++) q[d] = Qs[jq * HH + co + d];
        float sc[JJ];
        float mx = -1e30f;
#pragma unroll
        for (int k = 0; k < JJ; k++) {
            float s = 0.f;
#pragma unroll
            for (int d = 0; d < 16; d++) s += q[d] * Ks[k * HH + co + d];
            s *= 0.25f;
            sc[k] = s;
            mx = fmaxf(mx, s);
        }
        float l = 0.f;
#pragma unroll
        for (int k = 0; k < JJ; k++) {
            float p = __expf(sc[k] - mx);
            sc[k] = p;
            l += p;
        }
        float o[16];
#pragma unroll
        for (int d = 0; d < 16; d++) o[d] = 0.f;
#pragma unroll
        for (int k = 0; k < JJ; k++)
#pragma unroll
            for (int d = 0; d < 16; d++) o[d] += sc[k] * Vs[k * HH + co + d];
        float inv = 1.f / l;
#pragma unroll
        for (int d = 0; d < 16; d++) O[base + jq * HH + co + d] = o[d] * inv;
    }
}

// ---------------------------------------------------------------------------
// out_row = LayerNorm(A_row + B_row) * w + b   (rows of 128, one warp per row)
// ---------------------------------------------------------------------------
__global__ void ln_residual(const float* __restrict__ A, const float* __restrict__ B,
                            const float* __restrict__ w, const float* __restrict__ bb,
                            float* __restrict__ out) {
    int row  = blockIdx.x * 8 + (threadIdx.x >> 5);
    int lane = threadIdx.x & 31;
    long long off = (long long)row * HH + lane * 4;
    float4 va = *(const float4*)(A + off);
    float4 vb = *(const float4*)(B + off);
    float v0 = va.x + vb.x, v1 = va.y + vb.y, v2 = va.z + vb.z, v3 = va.w + vb.w;
    float s = v0 + v1 + v2 + v3;
#pragma unroll
    for (int o_ = 16; o_ > 0; o_ >>= 1) s += __shfl_xor_sync(0xffffffffu, s, o_);
    float mu = s * 0.0078125f;
    float d0 = v0 - mu, d1 = v1 - mu, d2 = v2 - mu, d3 = v3 - mu;
    float sq = d0 * d0 + d1 * d1 + d2 * d2 + d3 * d3;
#pragma unroll
    for (int o_ = 16; o_ > 0; o_ >>= 1) sq += __shfl_xor_sync(0xffffffffu, sq, o_);
    float rstd = rsqrtf(sq * 0.0078125f + 1e-5f);
    float4 wv = *(const float4*)(w + lane * 4);
    float4 bv = *(const float4*)(bb + lane * 4);
    float4 r;
    r.x = d0 * rstd * wv.x + bv.x;
    r.y = d1 * rstd * wv.y + bv.y;
    r.z = d2 * rstd * wv.z + bv.z;
    r.w = d3 * rstd * wv.w + bv.w;
    *(float4*)(out + off) = r;
}

__global__ void add2(const float* __restrict__ a, const float* __restrict__ b,
                     float* __restrict__ c) {
    long long i = (long long)blockIdx.x * blockDim.x + threadIdx.x;
    float4 va = ((const float4*)a)[i];
    float4 vb = ((const float4*)b)[i];
    ((float4*)c)[i] = make_float4(va.x + vb.x, va.y + vb.y, va.z + vb.z, va.w + vb.w);
}

// ---------------------------------------------------------------------------
extern "C" void kernel_launch(void* const* d_in, const int* in_sizes, int n_in,
                              void* d_out, int out_size) {
    const float* x        = (const float*)d_in[0];
    const float* q_t      = (const float*)d_in[2];
    const float* k_t      = (const float*)d_in[3];
    const float* v_t      = (const float*)d_in[4];
    const float* proj_t   = (const float*)d_in[5];
    const float* ln_t_w   = (const float*)d_in[6];
    const float* ln_t_b   = (const float*)d_in[7];
    const float* q_s      = (const float*)d_in[8];
    const float* k_s      = (const float*)d_in[9];
    const float* v_s      = (const float*)d_in[10];
    const float* proj_s_w = (const float*)d_in[11];
    const float* proj_s_b = (const float*)d_in[12];
    const float* ln_s_w   = (const float*)d_in[13];
    const float* ln_s_b   = (const float*)d_in[14];
    const float* ff1_w    = (const float*)d_in[15];
    const float* ff1_b    = (const float*)d_in[16];
    const float* ff2_w    = (const float*)d_in[17];
    const float* ff2_b    = (const float*)d_in[18];
    const float* ln_f_w   = (const float*)d_in[19];
    const float* ln_f_b   = (const float*)d_in[20];
    float* out = (float*)d_out;

    float* g = nullptr;
    cudaGetSymbolAddress((void**)&g, g_scratch);

    const int BIG = 1 << 30;
    const long long cHiT = (long long)JJ * SS * HH;   // temporal qkv b-stride
    const long long cJT  = (long long)SS * HH;        // temporal qkv j-stride

    // 0. pack weights
    pack_weights<<<(int)((WSZ + 255) / 256), 256>>>(q_t, k_t, v_t, q_s, k_s, v_s, g);

    // 1. temporal qkv: per-j GEMM, rows r=(b*S+s), out [b][j][s][c]
    dim3 gT(SS * BB / 128, JJ, 1);
    gemm128<<<gT, 256>>>(x, HH, JJ * HH, g + OFF_WQT, WJS, HH,
                         g + OFF_QT, cJT, HH, SS, cHiT, HH, nullptr, 0);
    gemm128<<<gT, 256>>>(x, HH, JJ * HH, g + OFF_WKT, WJS, HH,
                         g + OFF_KT, cJT, HH, SS, cHiT, HH, nullptr, 0);
    gemm128<<<gT, 256>>>(x, HH, JJ * HH, g + OFF_WVT, WJS, HH,
                         g + OFF_VT, cJT, HH, SS, cHiT, HH, nullptr, 0);

    // 2. temporal attention
    cudaFuncSetAttribute(temporal_attn, cudaFuncAttributeMaxDynamicSharedMemorySize, 65536);
    dim3 gA(1, NN, BB * JJ);
    temporal_attn<<<gA, 256, 65536>>>(g + OFF_QT, g + OFF_KT, g + OFF_VT, g + OFF_OT);

    // 3. temporal proj (per-j, A rows [b][s][j] stride JJ*HH) -> tmp, then LN(+x)
    gemm128<<<gT, 256>>>(g + OFF_OT, HH, JJ * HH, proj_t, (long long)HH * HH, HH,
                         g + OFF_TMP, HH, HH, BIG, 0, (long long)JJ * HH, nullptr, 0);
    ln_residual<<<BB * SS * JJ / 8, 256>>>(g + OFF_TMP, x, ln_t_w, ln_t_b, g + OFF_TOUT);

    // 4. spatial qkv
    gemm128<<<gT, 256>>>(x, HH, JJ * HH, g + OFF_WQS, WJS, HH,
                         g + OFF_QS, HH, HH, BIG, 0, (long long)JJ * HH, nullptr, 0);
    dim3 gF(BB * SS * JJ / 128, 1, 1);
    gemm128<<<gF, 256>>>(x, 0, HH, g + OFF_WKS, 0, HH,
                         g + OFF_KS, 0, HH, BIG, 0, HH, nullptr, 0);
    gemm128<<<gF, 256>>>(x, 0, HH, g + OFF_WVS, 0, HH,
                         g + OFF_VS, 0, HH, BIG, 0, HH, nullptr, 0);

    // 5. spatial attention
    spatial_attn<<<BB * SS, 256>>>(g + OFF_QS, g + OFF_KS, g + OFF_VS, g + OFF_OS);

    // 6. spatial proj + bias -> tmp, LN(+x) -> sout
    gemm128<<<gF, 256>>>(g + OFF_OS, 0, HH, proj_s_w, 0, HH,
                         g + OFF_TMP, 0, HH, BIG, 0, HH, proj_s_b, 0);
    ln_residual<<<BB * SS * JJ / 8, 256>>>(g + OFF_TMP, x, ln_s_w, ln_s_b, g + OFF_SOUT);

    // 7. a = t_out + s_out
    add2<<<(int)(E / 4 / 256), 256>>>(g + OFF_TOUT, g + OFF_SOUT, g + OFF_A);

    // 8. ff1 (+bias, relu): out cols 256 -> 2 col tiles
    dim3 gFF(BB * SS * JJ / 128, 1, 2);
    gemm128<<<gFF, 256>>>(g + OFF_A, 0, HH, ff1_w, 0, FDIM,
                          g + OFF_FFB, 0, HH, BIG, 0, FDIM, ff1_b, 1);

    // 9. ff2 (+bias) K=256 -> tmp, final LN(a + ff) -> out
    gemm128<<<gF, 256>>>(g + OFF_FFB, 0, FDIM, ff2_w, 0, HH,
                         g + OFF_TMP, 0, FDIM, BIG, 0, HH, ff2_b, 0);
    ln_residual<<<BB * SS * JJ / 8, 256>>>(g + OFF_A, g + OFF_TMP, ln_f_w, ln_f_b, out);
}